// round 7
// baseline (speedup 1.0000x reference)
#include <cuda_runtime.h>
#include <math.h>
#include <stdint.h>

// B=128, R=10, L=1024 -> M=1280 rows, K=2048, N=1024.
// score[b,i,j] = h_emb[b,j].v_h + q_emb[b,i].v_q + c  (pairwise MLP is linear)
// emb = tanh(X@Wy+by) * sigmoid(X@Wg+bg), fused into the GEMM epilogue.
// GEMM: mma.sync m16n8k32 int8, 64x64 dual-branch CTA, 4 CTA/SM,
// 4-stage cp.async pipeline (BK=64, 12KB/stage), one barrier per chunk.

#define KDIM 2048
#define NDIM 1024
#define MROWS 1280
#define BM 64
#define BN 64
#define BKC 64
#define NCHUNK (KDIM / BKC)         // 32

#define SX_BOUND 5.6f
#define SW_BOUND 0.11f
#define S_OUT ((SX_BOUND / 127.0f) * (SW_BOUND / 127.0f))

#define STAGE_A 0                   // 64 rows x 64B = 4096
#define STAGE_Y 4096
#define STAGE_G 8192
#define STAGE_BYTES 12288
#define NSTAGE 4
#define SMEM_TOTAL (NSTAGE * STAGE_BYTES)   // 49152

__device__ float g_v[2048];                 // v_h | v_q
__device__ float g_c;                       // mlp_b1 . mlp_w2 + mlp_b2
__device__ float g_s[2560];                 // row scores: hist | ques
__device__ int8_t g_xb[2][MROWS * KDIM];    // int8 X (K-major)
__device__ int8_t g_wt[4][NDIM * KDIM];     // int8 W^T [N,K] (K-major)

// ---------------------------------------------------------------------------
__device__ __forceinline__ uint32_t smem_u32(const void* p) {
    return (uint32_t)__cvta_generic_to_shared((void*)p);
}
__device__ __forceinline__ uint32_t swz64(uint32_t off) {
    return off ^ ((off >> 3) & 0x30);      // bits[5:4] ^= row[2:1] (64B rows)
}
__device__ __forceinline__ void cp16(uint32_t dst, const void* src) {
    asm volatile("cp.async.cg.shared.global [%0], [%1], 16;"
                 :: "r"(dst), "l"(src) : "memory");
}
__device__ __forceinline__ void ldsm_x4(uint32_t& r0, uint32_t& r1,
                                        uint32_t& r2, uint32_t& r3,
                                        uint32_t addr) {
    asm volatile("ldmatrix.sync.aligned.m8n8.x4.shared.b16 {%0,%1,%2,%3}, [%4];"
                 : "=r"(r0), "=r"(r1), "=r"(r2), "=r"(r3) : "r"(addr));
}
__device__ __forceinline__ void mma_s8(int* c, uint32_t a0, uint32_t a1,
                                       uint32_t a2, uint32_t a3,
                                       uint32_t b0, uint32_t b1) {
    asm volatile(
        "mma.sync.aligned.m16n8k32.row.col.s32.s8.s8.s32 "
        "{%0,%1,%2,%3}, {%4,%5,%6,%7}, {%8,%9}, {%0,%1,%2,%3};"
        : "+r"(c[0]), "+r"(c[1]), "+r"(c[2]), "+r"(c[3])
        : "r"(a0), "r"(a1), "r"(a2), "r"(a3), "r"(b0), "r"(b1));
}
__device__ __forceinline__ float tanh_fast(float x) {
    float y;
    asm("tanh.approx.f32 %0, %1;" : "=f"(y) : "f"(x));
    return y;
}
__device__ __forceinline__ float sigmoid_fast(float x) {
    return __fdividef(1.f, 1.f + __expf(-x));
}
__device__ __forceinline__ uint32_t q8w(float4 v, float inv_s) {
    int a = max(-127, min(127, __float2int_rn(v.x * inv_s)));
    int b = max(-127, min(127, __float2int_rn(v.y * inv_s)));
    int c = max(-127, min(127, __float2int_rn(v.z * inv_s)));
    int d = max(-127, min(127, __float2int_rn(v.w * inv_s)));
    uint32_t lo = __byte_perm((uint32_t)a, (uint32_t)b, 0x0040);
    uint32_t hi = __byte_perm((uint32_t)c, (uint32_t)d, 0x0040);
    return __byte_perm(lo, hi, 0x5410);
}

// ---------------------------------------------------------------------------
// prep_all: (a) X fp32->int8 [1280 blocks], (b) W fp32->int8 transposed with
// smem-staged coalesced writes [2048 blocks], (c) v = w1@w2 [256], (d) c [1].
// ---------------------------------------------------------------------------
__global__ void __launch_bounds__(256)
prep_all(const float* __restrict__ hist, const float* __restrict__ ques,
         const float* __restrict__ h_wy, const float* __restrict__ h_wg,
         const float* __restrict__ q_wy, const float* __restrict__ q_wg,
         const float* __restrict__ mlp_w1, const float* __restrict__ mlp_w2,
         const float* __restrict__ mlp_b1, const float* __restrict__ mlp_b2)
{
    const int bid = blockIdx.x, tid = threadIdx.x;

    if (bid < 1280) {
        const int z = bid >= 640;
        const float4* src = (const float4*)(z ? ques : hist);
        const int base4 = (bid - z * 640) * 1024 + tid * 4;
        const float inv = 127.0f / SX_BOUND;
        uint4 o;
        o.x = q8w(src[base4 + 0], inv);
        o.y = q8w(src[base4 + 1], inv);
        o.z = q8w(src[base4 + 2], inv);
        o.w = q8w(src[base4 + 3], inv);
        *(uint4*)(g_xb[z] + (size_t)(bid - z * 640) * 4096 + tid * 16) = o;
    } else if (bid < 3328) {
        __shared__ uint32_t ts[64][17];
        const int tb = bid - 1280;
        const int w = tb >> 9;
        const int rem = tb & 511;
        const int n0 = (rem & 15) * 64;
        const int k0 = (rem >> 4) * 64;
        const float* W = (w == 0) ? h_wy : (w == 1) ? h_wg
                       : (w == 2) ? q_wy : q_wg;
        const float inv = 127.0f / SW_BOUND;

        const int kg = tid >> 4, ng = tid & 15;
        const int kb = k0 + kg * 4, nb = ng * 4;
        uint32_t wrow[4];
        #pragma unroll
        for (int i = 0; i < 4; i++)
            wrow[i] = q8w(*(const float4*)(W + (size_t)(kb + i) * NDIM + n0 + nb), inv);
        #pragma unroll
        for (int j = 0; j < 4; j++) {
            uint32_t sel = (uint32_t)j | ((uint32_t)(4 + j) << 4);
            uint32_t p = __byte_perm(wrow[0], wrow[1], sel);
            uint32_t q = __byte_perm(wrow[2], wrow[3], sel);
            ts[nb + j][kg] = __byte_perm(p, q, 0x5410);
        }
        __syncthreads();
        {
            const int nr = tid >> 2, c = tid & 3;
            uint4 o;
            o.x = ts[nr][c * 4 + 0];
            o.y = ts[nr][c * 4 + 1];
            o.z = ts[nr][c * 4 + 2];
            o.w = ts[nr][c * 4 + 3];
            *(uint4*)(g_wt[w] + (size_t)(n0 + nr) * KDIM + k0 + c * 16) = o;
        }
    } else if (bid < 3584) {
        const int vb = bid - 3328;
        int gid = vb * 256 + tid;
        if (gid < 2560) g_s[gid] = 0.f;
        int warp = tid >> 5, lane = tid & 31;
        int k = vb * 8 + warp;
        const float4* row = (const float4*)(mlp_w1 + (size_t)k * NDIM);
        const float4* v2 = (const float4*)mlp_w2;
        float acc = 0.f;
        #pragma unroll
        for (int i = 0; i < 8; i++) {
            float4 a = row[lane + i * 32];
            float4 b = v2[lane + i * 32];
            acc += a.x * b.x + a.y * b.y + a.z * b.z + a.w * b.w;
        }
        #pragma unroll
        for (int o = 16; o; o >>= 1) acc += __shfl_xor_sync(0xffffffffu, acc, o);
        if (lane == 0) g_v[k] = acc;
    } else {
        __shared__ float sred[8];
        int warp = tid >> 5, lane = tid & 31;
        const float4* b1 = (const float4*)mlp_b1;
        const float4* v2 = (const float4*)mlp_w2;
        float4 a = b1[tid], b = v2[tid];
        float acc = a.x * b.x + a.y * b.y + a.z * b.z + a.w * b.w;
        #pragma unroll
        for (int o = 16; o; o >>= 1) acc += __shfl_xor_sync(0xffffffffu, acc, o);
        if (lane == 0) sred[warp] = acc;
        __syncthreads();
        if (tid == 0) {
            float s = 0.f;
            #pragma unroll
            for (int w = 0; w < 8; w++) s += sred[w];
            g_c = s + mlp_b2[0];
        }
    }
}

// ---------------------------------------------------------------------------
// gemm_mma: int8 dual GEMM 64x64, 4-stage cp.async pipeline, fused epilogue.
// grid (16 N, 20 M, 2 z) = 640 CTAs x 128 threads (4 warps, 2m x 2n).
// ---------------------------------------------------------------------------
__global__ void __launch_bounds__(128, 4)
gemm_mma(const float* __restrict__ by_h, const float* __restrict__ bg_h,
         const float* __restrict__ by_q, const float* __restrict__ bg_q)
{
    extern __shared__ char smem[];
    const uint32_t sb = smem_u32(smem);
    const int tid = threadIdx.x, wid = tid >> 5, lane = tid & 31;
    const int wm = wid & 1, wn = wid >> 1;
    const int z = blockIdx.z, bm = blockIdx.y, bn = blockIdx.x;

    const int8_t* A  = g_xb[z]         + (size_t)(bm * BM) * KDIM;
    const int8_t* Wy = g_wt[z * 2 + 0] + (size_t)(bn * BN) * KDIM;
    const int8_t* Wg = g_wt[z * 2 + 1] + (size_t)(bn * BN) * KDIM;

    const int ldrow = tid >> 2;            // 0..31 (+32 second iter)
    const int ldchunk = tid & 3;           // 16B chunk in 64B row

    auto issue = [&](int ch) {
        const uint32_t stage = sb + (ch & (NSTAGE - 1)) * STAGE_BYTES;
        const int k0 = ch * BKC;
        #pragma unroll
        for (int l = 0; l < 2; l++) {
            int row = ldrow + l * 32;
            uint32_t off = swz64(row * 64 + ldchunk * 16);
            const size_t go = (size_t)row * KDIM + k0 + ldchunk * 16;
            cp16(stage + STAGE_A + off, A + go);
            cp16(stage + STAGE_Y + off, Wy + go);
            cp16(stage + STAGE_G + off, Wg + go);
        }
        asm volatile("cp.async.commit_group;" ::: "memory");
    };

    // epilogue constants (L2-resident, independent of mainloop)
    const float* by = z ? by_q : by_h;
    const float* bg = z ? bg_q : bg_h;
    const float* vv = g_v + z * 1024;
    float byv[4][2], bgv[4][2], vvv[4][2];
    #pragma unroll
    for (int ni = 0; ni < 4; ni++)
        #pragma unroll
        for (int c = 0; c < 2; c++) {
            int col = bn * BN + wn * 32 + ni * 8 + (lane & 3) * 2 + c;
            byv[ni][c] = __ldg(by + col);
            bgv[ni][c] = __ldg(bg + col);
            vvv[ni][c] = __ldg(vv + col);
        }

    int accY[2][4][4], accG[2][4][4];
    #pragma unroll
    for (int mi = 0; mi < 2; mi++)
        #pragma unroll
        for (int ni = 0; ni < 4; ni++)
            #pragma unroll
            for (int c = 0; c < 4; c++) { accY[mi][ni][c] = 0; accG[mi][ni][c] = 0; }

    const int a_row = wm * 32 + (lane & 15);
    const int a_k16 = (lane >> 4) * 16;
    const int b_row = wn * 32 + ((lane >> 4) * 8) + (lane & 7);
    const int b_k16 = ((lane >> 3) & 1) * 16;

    issue(0);
    issue(1);
    issue(2);

    for (int ch = 0; ch < NCHUNK; ch++) {
        // 3 groups pending (real or empty) -> wait_group 2 means chunk ch done
        asm volatile("cp.async.wait_group 2;" ::: "memory");
        __syncthreads();
        if (ch + 3 < NCHUNK) issue(ch + 3);
        else asm volatile("cp.async.commit_group;" ::: "memory");

        const uint32_t stage = sb + (ch & (NSTAGE - 1)) * STAGE_BYTES;
        #pragma unroll
        for (int ks = 0; ks < 2; ks++) {
            const int kb = ks * 32;
            uint32_t a0[4], a1[4];
            ldsm_x4(a0[0], a0[1], a0[2], a0[3],
                    stage + STAGE_A + swz64(a_row * 64 + kb + a_k16));
            ldsm_x4(a1[0], a1[1], a1[2], a1[3],
                    stage + STAGE_A + swz64((a_row + 16) * 64 + kb + a_k16));
            uint32_t by0[4], by1[4], bg0[4], bg1[4];
            ldsm_x4(by0[0], by0[1], by0[2], by0[3],
                    stage + STAGE_Y + swz64(b_row * 64 + kb + b_k16));
            ldsm_x4(by1[0], by1[1], by1[2], by1[3],
                    stage + STAGE_Y + swz64((b_row + 16) * 64 + kb + b_k16));
            ldsm_x4(bg0[0], bg0[1], bg0[2], bg0[3],
                    stage + STAGE_G + swz64(b_row * 64 + kb + b_k16));
            ldsm_x4(bg1[0], bg1[1], bg1[2], bg1[3],
                    stage + STAGE_G + swz64((b_row + 16) * 64 + kb + b_k16));

            #pragma unroll
            for (int mi = 0; mi < 2; mi++) {
                uint32_t* a = mi ? a1 : a0;
                mma_s8(accY[mi][0], a[0], a[1], a[2], a[3], by0[0], by0[1]);
                mma_s8(accY[mi][1], a[0], a[1], a[2], a[3], by0[2], by0[3]);
                mma_s8(accY[mi][2], a[0], a[1], a[2], a[3], by1[0], by1[1]);
                mma_s8(accY[mi][3], a[0], a[1], a[2], a[3], by1[2], by1[3]);
                mma_s8(accG[mi][0], a[0], a[1], a[2], a[3], bg0[0], bg0[1]);
                mma_s8(accG[mi][1], a[0], a[1], a[2], a[3], bg0[2], bg0[3]);
                mma_s8(accG[mi][2], a[0], a[1], a[2], a[3], bg1[0], bg1[1]);
                mma_s8(accG[mi][3], a[0], a[1], a[2], a[3], bg1[2], bg1[3]);
            }
        }
    }

    // ---- fused epilogue: dequant -> tanh*sigmoid -> rowsum(act*v) ----
    #pragma unroll
    for (int mi = 0; mi < 2; mi++) {
        float s0 = 0.f, s1 = 0.f;
        #pragma unroll
        for (int ni = 0; ni < 4; ni++)
            #pragma unroll
            for (int c = 0; c < 2; c++) {
                float y0 = (float)accY[mi][ni][c]     * S_OUT + byv[ni][c];
                float g0 = (float)accG[mi][ni][c]     * S_OUT + bgv[ni][c];
                s0 += tanh_fast(y0) * sigmoid_fast(g0) * vvv[ni][c];
                float y1 = (float)accY[mi][ni][2 + c] * S_OUT + byv[ni][c];
                float g1 = (float)accG[mi][ni][2 + c] * S_OUT + bgv[ni][c];
                s1 += tanh_fast(y1) * sigmoid_fast(g1) * vvv[ni][c];
            }
        s0 += __shfl_xor_sync(0xffffffffu, s0, 1);
        s0 += __shfl_xor_sync(0xffffffffu, s0, 2);
        s1 += __shfl_xor_sync(0xffffffffu, s1, 1);
        s1 += __shfl_xor_sync(0xffffffffu, s1, 2);
        if ((lane & 3) == 0) {
            int r0 = bm * BM + wm * 32 + mi * 16 + (lane >> 2);
            atomicAdd(&g_s[z * MROWS + r0], s0);
            atomicAdd(&g_s[z * MROWS + r0 + 8], s1);
        }
    }
}

// ---------------------------------------------------------------------------
// epilogue_kernel: per-batch causal Gumbel-softmax (10x10).
// ---------------------------------------------------------------------------
__global__ void epilogue_kernel(
    const float* __restrict__ gumbel,
    const float* __restrict__ att_w, const float* __restrict__ att_b,
    float* __restrict__ out)
{
    __shared__ float sh[10], sq[10];
    const int b = blockIdx.x, tid = threadIdx.x;

    if (tid < 10) {
        sh[tid] = g_s[b * 10 + tid];
        sq[tid] = g_s[1280 + b * 10 + tid];
    }
    __syncthreads();

    const float sc = g_c;
    const float w0 = att_w[0], w1 = att_w[1], ab = att_b[0];
    if (tid < 10) {
        const int i = tid;
        float y[10];
        float m = -1e30f;
        for (int j = 0; j <= i; j++) {
            float score = sh[j] + sq[i] + sc;
            float dt = (float)(i - j + 1);
            float u = gumbel[(b * 10 + i) * 10 + j];
            float g = -logf(-logf(u + 1e-20f) + 1e-20f);
            float yy = score * w0 + dt * w1 + ab + g;
            y[j] = yy;
            m = fmaxf(m, yy);
        }
        float ssum = 0.f;
        for (int j = 0; j <= i; j++) { y[j] = expf(y[j] - m); ssum += y[j]; }
        float inv = 1.f / ssum;
        for (int j = 0; j < 10; j++)
            out[(b * 10 + i) * 10 + j] = (j <= i) ? y[j] * inv : 0.f;
    }
}

// ---------------------------------------------------------------------------
extern "C" void kernel_launch(void* const* d_in, const int* in_sizes, int n_in,
                              void* d_out, int out_size) {
    const float* hist   = (const float*)d_in[0];
    const float* ques   = (const float*)d_in[1];
    const float* gumbel = (const float*)d_in[2];
    const float* h_wy   = (const float*)d_in[3];
    const float* h_by   = (const float*)d_in[4];
    const float* h_wg   = (const float*)d_in[5];
    const float* h_bg   = (const float*)d_in[6];
    const float* q_wy   = (const float*)d_in[7];
    const float* q_by   = (const float*)d_in[8];
    const float* q_wg   = (const float*)d_in[9];
    const float* q_bg   = (const float*)d_in[10];
    const float* mlp_w1 = (const float*)d_in[11];
    const float* mlp_b1 = (const float*)d_in[12];
    const float* mlp_w2 = (const float*)d_in[13];
    const float* mlp_b2 = (const float*)d_in[14];
    const float* att_w  = (const float*)d_in[15];
    const float* att_b  = (const float*)d_in[16];
    float* out = (float*)d_out;

    cudaFuncSetAttribute(gemm_mma, cudaFuncAttributeMaxDynamicSharedMemorySize,
                         SMEM_TOTAL);

    prep_all<<<3585, 256>>>(hist, ques, h_wy, h_wg, q_wy, q_wg,
                            mlp_w1, mlp_w2, mlp_b1, mlp_b2);
    gemm_mma<<<dim3(16, 20, 2), 128, SMEM_TOTAL>>>(h_by, h_bg, q_by, q_bg);
    epilogue_kernel<<<128, 128>>>(gumbel, att_w, att_b, out);
}

// round 9
// speedup vs baseline: 1.1243x; 1.1243x over previous
#include <cuda_runtime.h>
#include <math.h>
#include <stdint.h>

// B=128, R=10, L=1024 -> M=1280 rows, K=2048, N=1024.
// score[b,i,j] = h_emb[b,j].v_h + q_emb[b,i].v_q + c  (pairwise MLP is linear)
// emb = tanh(X@Wy+by) * sigmoid(X@Wg+bg), fused into the GEMM epilogue.
// GEMM: mma.sync m16n8k32 int8. BM=160 x BN=64 dual-branch, 128 thr,
// 2 CTA/SM, 2-stage cp.async (R6 structure). Traffic 252 -> 151 MB.

#define KDIM 2048
#define NDIM 1024
#define MROWS 1280
#define BM 160
#define BN 64
#define BKC 128
#define NCHUNK (KDIM / BKC)         // 16

#define SX_BOUND 5.6f
#define SW_BOUND 0.11f
#define S_OUT ((SX_BOUND / 127.0f) * (SW_BOUND / 127.0f))

#define STAGE_A 0                   // 160 rows x 128B = 20480
#define STAGE_Y 20480               // 64 rows x 128B  = 8192
#define STAGE_G 28672
#define STAGE_BYTES 36864
#define SMEM_TOTAL (2 * STAGE_BYTES)   // 73728

__device__ float g_v[2048];                 // v_h | v_q
__device__ float g_c;                       // mlp_b1 . mlp_w2 + mlp_b2
__device__ float g_s[2560];                 // row scores: hist | ques
__device__ int8_t g_xb[2][MROWS * KDIM];    // int8 X (K-major)
__device__ int8_t g_wt[4][NDIM * KDIM];     // int8 W^T [N,K] (K-major)

// ---------------------------------------------------------------------------
__device__ __forceinline__ uint32_t smem_u32(const void* p) {
    return (uint32_t)__cvta_generic_to_shared((void*)p);
}
__device__ __forceinline__ uint32_t swz(uint32_t off) {
    return off ^ ((off >> 3) & 0x70);      // SW128 for 128B rows
}
__device__ __forceinline__ void cp16(uint32_t dst, const void* src) {
    asm volatile("cp.async.cg.shared.global [%0], [%1], 16;"
                 :: "r"(dst), "l"(src) : "memory");
}
__device__ __forceinline__ void ldsm_x4(uint32_t& r0, uint32_t& r1,
                                        uint32_t& r2, uint32_t& r3,
                                        uint32_t addr) {
    asm volatile("ldmatrix.sync.aligned.m8n8.x4.shared.b16 {%0,%1,%2,%3}, [%4];"
                 : "=r"(r0), "=r"(r1), "=r"(r2), "=r"(r3) : "r"(addr));
}
__device__ __forceinline__ void mma_s8(int* c, uint32_t a0, uint32_t a1,
                                       uint32_t a2, uint32_t a3,
                                       uint32_t b0, uint32_t b1) {
    asm volatile(
        "mma.sync.aligned.m16n8k32.row.col.s32.s8.s8.s32 "
        "{%0,%1,%2,%3}, {%4,%5,%6,%7}, {%8,%9}, {%0,%1,%2,%3};"
        : "+r"(c[0]), "+r"(c[1]), "+r"(c[2]), "+r"(c[3])
        : "r"(a0), "r"(a1), "r"(a2), "r"(a3), "r"(b0), "r"(b1));
}
__device__ __forceinline__ float tanh_fast(float x) {
    float y;
    asm("tanh.approx.f32 %0, %1;" : "=f"(y) : "f"(x));
    return y;
}
__device__ __forceinline__ float sigmoid_fast(float x) {
    return __fdividef(1.f, 1.f + __expf(-x));
}
__device__ __forceinline__ uint32_t q8w(float4 v, float inv_s) {
    int a = max(-127, min(127, __float2int_rn(v.x * inv_s)));
    int b = max(-127, min(127, __float2int_rn(v.y * inv_s)));
    int c = max(-127, min(127, __float2int_rn(v.z * inv_s)));
    int d = max(-127, min(127, __float2int_rn(v.w * inv_s)));
    uint32_t lo = __byte_perm((uint32_t)a, (uint32_t)b, 0x0040);
    uint32_t hi = __byte_perm((uint32_t)c, (uint32_t)d, 0x0040);
    return __byte_perm(lo, hi, 0x5410);
}

// ---------------------------------------------------------------------------
// prep_all: (a) X fp32->int8 [1280 blocks], (b) W fp32->int8 transposed with
// smem-staged coalesced writes [2048 blocks], (c) v = w1@w2 [256], (d) c [1].
// ---------------------------------------------------------------------------
__global__ void __launch_bounds__(256)
prep_all(const float* __restrict__ hist, const float* __restrict__ ques,
         const float* __restrict__ h_wy, const float* __restrict__ h_wg,
         const float* __restrict__ q_wy, const float* __restrict__ q_wg,
         const float* __restrict__ mlp_w1, const float* __restrict__ mlp_w2,
         const float* __restrict__ mlp_b1, const float* __restrict__ mlp_b2)
{
    const int bid = blockIdx.x, tid = threadIdx.x;

    if (bid < 1280) {
        const int z = bid >= 640;
        const float4* src = (const float4*)(z ? ques : hist);
        const int base4 = (bid - z * 640) * 1024 + tid * 4;
        const float inv = 127.0f / SX_BOUND;
        uint4 o;
        o.x = q8w(src[base4 + 0], inv);
        o.y = q8w(src[base4 + 1], inv);
        o.z = q8w(src[base4 + 2], inv);
        o.w = q8w(src[base4 + 3], inv);
        *(uint4*)(g_xb[z] + (size_t)(bid - z * 640) * 4096 + tid * 16) = o;
    } else if (bid < 3328) {
        __shared__ uint32_t ts[64][17];
        const int tb = bid - 1280;
        const int w = tb >> 9;
        const int rem = tb & 511;
        const int n0 = (rem & 15) * 64;
        const int k0 = (rem >> 4) * 64;
        const float* W = (w == 0) ? h_wy : (w == 1) ? h_wg
                       : (w == 2) ? q_wy : q_wg;
        const float inv = 127.0f / SW_BOUND;

        const int kg = tid >> 4, ng = tid & 15;
        const int kb = k0 + kg * 4, nb = ng * 4;
        uint32_t wrow[4];
        #pragma unroll
        for (int i = 0; i < 4; i++)
            wrow[i] = q8w(*(const float4*)(W + (size_t)(kb + i) * NDIM + n0 + nb), inv);
        #pragma unroll
        for (int j = 0; j < 4; j++) {
            uint32_t sel = (uint32_t)j | ((uint32_t)(4 + j) << 4);
            uint32_t p = __byte_perm(wrow[0], wrow[1], sel);
            uint32_t q = __byte_perm(wrow[2], wrow[3], sel);
            ts[nb + j][kg] = __byte_perm(p, q, 0x5410);
        }
        __syncthreads();
        {
            const int nr = tid >> 2, c = tid & 3;
            uint4 o;
            o.x = ts[nr][c * 4 + 0];
            o.y = ts[nr][c * 4 + 1];
            o.z = ts[nr][c * 4 + 2];
            o.w = ts[nr][c * 4 + 3];
            *(uint4*)(g_wt[w] + (size_t)(n0 + nr) * KDIM + k0 + c * 16) = o;
        }
    } else if (bid < 3584) {
        const int vb = bid - 3328;
        int gid = vb * 256 + tid;
        if (gid < 2560) g_s[gid] = 0.f;
        int warp = tid >> 5, lane = tid & 31;
        int k = vb * 8 + warp;
        const float4* row = (const float4*)(mlp_w1 + (size_t)k * NDIM);
        const float4* v2 = (const float4*)mlp_w2;
        float acc = 0.f;
        #pragma unroll
        for (int i = 0; i < 8; i++) {
            float4 a = row[lane + i * 32];
            float4 b = v2[lane + i * 32];
            acc += a.x * b.x + a.y * b.y + a.z * b.z + a.w * b.w;
        }
        #pragma unroll
        for (int o = 16; o; o >>= 1) acc += __shfl_xor_sync(0xffffffffu, acc, o);
        if (lane == 0) g_v[k] = acc;
    } else {
        __shared__ float sred[8];
        int warp = tid >> 5, lane = tid & 31;
        const float4* b1 = (const float4*)mlp_b1;
        const float4* v2 = (const float4*)mlp_w2;
        float4 a = b1[tid], b = v2[tid];
        float acc = a.x * b.x + a.y * b.y + a.z * b.z + a.w * b.w;
        #pragma unroll
        for (int o = 16; o; o >>= 1) acc += __shfl_xor_sync(0xffffffffu, acc, o);
        if (lane == 0) sred[warp] = acc;
        __syncthreads();
        if (tid == 0) {
            float s = 0.f;
            #pragma unroll
            for (int w = 0; w < 8; w++) s += sred[w];
            g_c = s + mlp_b2[0];
        }
    }
}

// ---------------------------------------------------------------------------
// gemm_mma: int8 dual GEMM 160x64, 2-stage pipeline, fused epilogue.
// grid (16 N, 8 M, 2 z) = 256 CTAs x 128 threads (4 warps, 2m x 2n).
// Warp tile: 80(m) x 32(n) per branch = 5 m-frags x 4 n-frags.
// ---------------------------------------------------------------------------
__global__ void __launch_bounds__(128, 2)
gemm_mma(const float* __restrict__ by_h, const float* __restrict__ bg_h,
         const float* __restrict__ by_q, const float* __restrict__ bg_q)
{
    extern __shared__ char smem[];
    const uint32_t sb = smem_u32(smem);
    const int tid = threadIdx.x, wid = tid >> 5, lane = tid & 31;
    const int wm = wid & 1, wn = wid >> 1;
    const int z = blockIdx.z, bm = blockIdx.y, bn = blockIdx.x;

    const int8_t* A  = g_xb[z]         + (size_t)(bm * BM) * KDIM;
    const int8_t* Wy = g_wt[z * 2 + 0] + (size_t)(bn * BN) * KDIM;
    const int8_t* Wg = g_wt[z * 2 + 1] + (size_t)(bn * BN) * KDIM;

    const int ldrow = tid >> 3;            // 0..15
    const int ldchunk = tid & 7;           // 16B chunk in 128B row

    auto issue = [&](int ch) {
        const uint32_t stage = sb + (ch & 1) * STAGE_BYTES;
        const int k0 = ch * BKC;
        #pragma unroll
        for (int l = 0; l < 10; l++) {     // A: 160 rows
            int row = ldrow + l * 16;
            uint32_t off = swz(row * 128 + ldchunk * 16);
            cp16(stage + STAGE_A + off, A + (size_t)row * KDIM + k0 + ldchunk * 16);
        }
        #pragma unroll
        for (int l = 0; l < 4; l++) {      // Wy, Wg: 64 rows each
            int row = ldrow + l * 16;
            uint32_t off = swz(row * 128 + ldchunk * 16);
            const size_t go = (size_t)row * KDIM + k0 + ldchunk * 16;
            cp16(stage + STAGE_Y + off, Wy + go);
            cp16(stage + STAGE_G + off, Wg + go);
        }
        asm volatile("cp.async.commit_group;" ::: "memory");
    };

    // epilogue constants (L2-resident, independent of mainloop)
    const float* by = z ? by_q : by_h;
    const float* bg = z ? bg_q : bg_h;
    const float* vv = g_v + z * 1024;
    float byv[4][2], bgv[4][2], vvv[4][2];
    #pragma unroll
    for (int ni = 0; ni < 4; ni++)
        #pragma unroll
        for (int c = 0; c < 2; c++) {
            int col = bn * BN + wn * 32 + ni * 8 + (lane & 3) * 2 + c;
            byv[ni][c] = __ldg(by + col);
            bgv[ni][c] = __ldg(bg + col);
            vvv[ni][c] = __ldg(vv + col);
        }

    int accY[5][4][4], accG[5][4][4];
    #pragma unroll
    for (int mi = 0; mi < 5; mi++)
        #pragma unroll
        for (int ni = 0; ni < 4; ni++)
            #pragma unroll
            for (int c = 0; c < 4; c++) { accY[mi][ni][c] = 0; accG[mi][ni][c] = 0; }

    const int a_row = wm * 80 + (lane & 15);
    const int a_k16 = (lane >> 4) * 16;
    const int b_row = wn * 32 + ((lane >> 4) * 8) + (lane & 7);
    const int b_k16 = ((lane >> 3) & 1) * 16;

    issue(0);

    for (int ch = 0; ch < NCHUNK; ch++) {
        __syncthreads();
        if (ch + 1 < NCHUNK) {
            issue(ch + 1);
            asm volatile("cp.async.wait_group 1;" ::: "memory");
        } else {
            asm volatile("cp.async.wait_group 0;" ::: "memory");
        }
        __syncthreads();

        const uint32_t stage = sb + (ch & 1) * STAGE_BYTES;
        #pragma unroll
        for (int ks = 0; ks < 4; ks++) {
            const int kb = ks * 32;
            uint32_t by0[4], by1[4], bg0[4], bg1[4];
            ldsm_x4(by0[0], by0[1], by0[2], by0[3],
                    stage + STAGE_Y + swz(b_row * 128 + kb + b_k16));
            ldsm_x4(by1[0], by1[1], by1[2], by1[3],
                    stage + STAGE_Y + swz((b_row + 16) * 128 + kb + b_k16));
            ldsm_x4(bg0[0], bg0[1], bg0[2], bg0[3],
                    stage + STAGE_G + swz(b_row * 128 + kb + b_k16));
            ldsm_x4(bg1[0], bg1[1], bg1[2], bg1[3],
                    stage + STAGE_G + swz((b_row + 16) * 128 + kb + b_k16));

            #pragma unroll
            for (int mi = 0; mi < 5; mi++) {
                uint32_t a[4];
                ldsm_x4(a[0], a[1], a[2], a[3],
                        stage + STAGE_A + swz((a_row + mi * 16) * 128 + kb + a_k16));
                mma_s8(accY[mi][0], a[0], a[1], a[2], a[3], by0[0], by0[1]);
                mma_s8(accY[mi][1], a[0], a[1], a[2], a[3], by0[2], by0[3]);
                mma_s8(accY[mi][2], a[0], a[1], a[2], a[3], by1[0], by1[1]);
                mma_s8(accY[mi][3], a[0], a[1], a[2], a[3], by1[2], by1[3]);
                mma_s8(accG[mi][0], a[0], a[1], a[2], a[3], bg0[0], bg0[1]);
                mma_s8(accG[mi][1], a[0], a[1], a[2], a[3], bg0[2], bg0[3]);
                mma_s8(accG[mi][2], a[0], a[1], a[2], a[3], bg1[0], bg1[1]);
                mma_s8(accG[mi][3], a[0], a[1], a[2], a[3], bg1[2], bg1[3]);
            }
        }
    }

    // ---- fused epilogue: dequant -> tanh*sigmoid -> rowsum(act*v) ----
    #pragma unroll
    for (int mi = 0; mi < 5; mi++) {
        float s0 = 0.f, s1 = 0.f;
        #pragma unroll
        for (int ni = 0; ni < 4; ni++)
            #pragma unroll
            for (int c = 0; c < 2; c++) {
                float y0 = (float)accY[mi][ni][c]     * S_OUT + byv[ni][c];
                float g0 = (float)accG[mi][ni][c]     * S_OUT + bgv[ni][c];
                s0 += tanh_fast(y0) * sigmoid_fast(g0) * vvv[ni][c];
                float y1 = (float)accY[mi][ni][2 + c] * S_OUT + byv[ni][c];
                float g1 = (float)accG[mi][ni][2 + c] * S_OUT + bgv[ni][c];
                s1 += tanh_fast(y1) * sigmoid_fast(g1) * vvv[ni][c];
            }
        s0 += __shfl_xor_sync(0xffffffffu, s0, 1);
        s0 += __shfl_xor_sync(0xffffffffu, s0, 2);
        s1 += __shfl_xor_sync(0xffffffffu, s1, 1);
        s1 += __shfl_xor_sync(0xffffffffu, s1, 2);
        if ((lane & 3) == 0) {
            int r0 = bm * BM + wm * 80 + mi * 16 + (lane >> 2);
            atomicAdd(&g_s[z * MROWS + r0], s0);
            atomicAdd(&g_s[z * MROWS + r0 + 8], s1);
        }
    }
}

// ---------------------------------------------------------------------------
// epilogue_kernel: per-batch causal Gumbel-softmax (10x10).
// ---------------------------------------------------------------------------
__global__ void epilogue_kernel(
    const float* __restrict__ gumbel,
    const float* __restrict__ att_w, const float* __restrict__ att_b,
    float* __restrict__ out)
{
    __shared__ float sh[10], sq[10];
    const int b = blockIdx.x, tid = threadIdx.x;

    if (tid < 10) {
        sh[tid] = g_s[b * 10 + tid];
        sq[tid] = g_s[1280 + b * 10 + tid];
    }
    __syncthreads();

    const float sc = g_c;
    const float w0 = att_w[0], w1 = att_w[1], ab = att_b[0];
    if (tid < 10) {
        const int i = tid;
        float y[10];
        float m = -1e30f;
        for (int j = 0; j <= i; j++) {
            float score = sh[j] + sq[i] + sc;
            float dt = (float)(i - j + 1);
            float u = gumbel[(b * 10 + i) * 10 + j];
            float g = -logf(-logf(u + 1e-20f) + 1e-20f);
            float yy = score * w0 + dt * w1 + ab + g;
            y[j] = yy;
            m = fmaxf(m, yy);
        }
        float ssum = 0.f;
        for (int j = 0; j <= i; j++) { y[j] = expf(y[j] - m); ssum += y[j]; }
        float inv = 1.f / ssum;
        for (int j = 0; j < 10; j++)
            out[(b * 10 + i) * 10 + j] = (j <= i) ? y[j] * inv : 0.f;
    }
}

// ---------------------------------------------------------------------------
extern "C" void kernel_launch(void* const* d_in, const int* in_sizes, int n_in,
                              void* d_out, int out_size) {
    const float* hist   = (const float*)d_in[0];
    const float* ques   = (const float*)d_in[1];
    const float* gumbel = (const float*)d_in[2];
    const float* h_wy   = (const float*)d_in[3];
    const float* h_by   = (const float*)d_in[4];
    const float* h_wg   = (const float*)d_in[5];
    const float* h_bg   = (const float*)d_in[6];
    const float* q_wy   = (const float*)d_in[7];
    const float* q_by   = (const float*)d_in[8];
    const float* q_wg   = (const float*)d_in[9];
    const float* q_bg   = (const float*)d_in[10];
    const float* mlp_w1 = (const float*)d_in[11];
    const float* mlp_b1 = (const float*)d_in[12];
    const float* mlp_w2 = (const float*)d_in[13];
    const float* mlp_b2 = (const float*)d_in[14];
    const float* att_w  = (const float*)d_in[15];
    const float* att_b  = (const float*)d_in[16];
    float* out = (float*)d_out;

    cudaFuncSetAttribute(gemm_mma, cudaFuncAttributeMaxDynamicSharedMemorySize,
                         SMEM_TOTAL);

    prep_all<<<3585, 256>>>(hist, ques, h_wy, h_wg, q_wy, q_wg,
                            mlp_w1, mlp_w2, mlp_b1, mlp_b2);
    gemm_mma<<<dim3(16, 8, 2), 128, SMEM_TOTAL>>>(h_by, h_bg, q_by, q_bg);
    epilogue_kernel<<<128, 128>>>(gumbel, att_w, att_b, out);
}